// round 5
// baseline (speedup 1.0000x reference)
#include <cuda_runtime.h>

// Inverse Haar (db1) 2D wavelet step, grouped transposed conv stride2/kernel2.
// Input  x: (16, 128, 128, 128) f32  -> channel pairs (2g, 2g+1)
// Filters:  (2, 2, 2) f32            -> f[c*4 + i*2 + j]
// Output:   (16, 64, 256, 256) f32
//
// out[b,g,2h+i,2w+j] = x[b,2g,h,w]*f0[i,j] + x[b,2g+1,h,w]*f1[i,j]
//
// Pure streaming kernel: 134 MB read + 268 MB write, zero reuse -> HBM-bound.
// Each thread: 4 input columns (float4 x2 loads), writes 2 rows x 8 floats
// (4x float4 stores). Fully coalesced both directions.

#define HW_IN   (128 * 128)      // input plane elements
#define HW_OUT  (256 * 256)      // output plane elements
#define W_IN    128
#define W_OUT   256

__global__ __launch_bounds__(256) void iwt_kernel(
    const float* __restrict__ x,
    const float* __restrict__ f,
    float* __restrict__ out)
{
    int tid = blockIdx.x * blockDim.x + threadIdx.x;
    // tid = ((bg * 128) + h) * 32 + w4 ; bg = b*64+g in [0,1024)
    int w4 = tid & 31;          // which float4 along w (w = 4*w4)
    int h  = (tid >> 5) & 127;
    int bg = tid >> 12;

    // Filter coefficients (broadcast, L1-resident).
    const float f00 = __ldg(f + 0), f01 = __ldg(f + 1);
    const float f10 = __ldg(f + 2), f11 = __ldg(f + 3);
    const float g00 = __ldg(f + 4), g01 = __ldg(f + 5);
    const float g10 = __ldg(f + 6), g11 = __ldg(f + 7);

    // Input channel index for (b,g) pair 0 is 2*bg (since b*128 + 2g = 2*(b*64+g)).
    int in_base = 2 * bg * HW_IN + h * W_IN + (w4 << 2);
    float4 a = *reinterpret_cast<const float4*>(x + in_base);          // channel 2g
    float4 b = *reinterpret_cast<const float4*>(x + in_base + HW_IN);  // channel 2g+1

    // Output block: rows 2h and 2h+1, columns [8*w4, 8*w4+8)
    int out_base = bg * HW_OUT + (h << 1) * W_OUT + (w4 << 3);

    float4 t0 = make_float4(fmaf(b.x, g00, a.x * f00), fmaf(b.x, g01, a.x * f01),
                            fmaf(b.y, g00, a.y * f00), fmaf(b.y, g01, a.y * f01));
    float4 t1 = make_float4(fmaf(b.z, g00, a.z * f00), fmaf(b.z, g01, a.z * f01),
                            fmaf(b.w, g00, a.w * f00), fmaf(b.w, g01, a.w * f01));
    float4 u0 = make_float4(fmaf(b.x, g10, a.x * f10), fmaf(b.x, g11, a.x * f11),
                            fmaf(b.y, g10, a.y * f10), fmaf(b.y, g11, a.y * f11));
    float4 u1 = make_float4(fmaf(b.z, g10, a.z * f10), fmaf(b.z, g11, a.z * f11),
                            fmaf(b.w, g10, a.w * f10), fmaf(b.w, g11, a.w * f11));

    float4* orow0 = reinterpret_cast<float4*>(out + out_base);
    float4* orow1 = reinterpret_cast<float4*>(out + out_base + W_OUT);
    orow0[0] = t0;
    orow0[1] = t1;
    orow1[0] = u0;
    orow1[1] = u1;
}

extern "C" void kernel_launch(void* const* d_in, const int* in_sizes, int n_in,
                              void* d_out, int out_size) {
    const float* x = (const float*)d_in[0];          // (16,128,128,128) f32
    const float* f = (const float*)d_in[1];          // (2,2,2) f32
    float* out = (float*)d_out;                      // (16,64,256,256) f32

    // total threads = 16*64 * 128 * 32 = 4,194,304
    const int total = 16 * 64 * 128 * 32;
    const int tpb = 256;
    iwt_kernel<<<total / tpb, tpb>>>(x, f, out);
}

// round 6
// speedup vs baseline: 1.6486x; 1.6486x over previous
#include <cuda_runtime.h>

// Inverse Haar (db1) 2D wavelet step, grouped transposed conv stride2/kernel2.
// Input  x: (16, 128, 128, 128) f32  -> channel pairs (2g, 2g+1)
// Filters:  (2, 2, 2) f32            -> f[c*4 + i*2 + j]
// Output:   (16, 64, 256, 256) f32
//
// out[b,g,2h+i,2w+j] = x[b,2g,h,w]*f0[i,j] + x[b,2g+1,h,w]*f1[i,j]
//
// R5: warp-dense stores. Thread i owns output float4-columns {i, 32+i} of the
// two output rows, so every STG.128 is 512B contiguous per warp (4 full lines)
// instead of the previous stride-32B half-dense pattern (8 half lines).
// Inputs become 4 independent LDG.64 (MLP=4), each 256B contiguous per warp.

#define HW_IN   (128 * 128)
#define HW_OUT  (256 * 256)
#define W_IN    128
#define W_OUT   256

__global__ __launch_bounds__(256) void iwt_kernel(
    const float* __restrict__ x,
    const float* __restrict__ f,
    float* __restrict__ out)
{
    int tid = blockIdx.x * blockDim.x + threadIdx.x;
    int i  = tid & 31;           // lane's float4-column slot
    int h  = (tid >> 5) & 127;   // input row
    int bg = tid >> 12;          // b*64 + g in [0,1024)

    const float f00 = __ldg(f + 0), f01 = __ldg(f + 1);
    const float f10 = __ldg(f + 2), f11 = __ldg(f + 3);
    const float g00 = __ldg(f + 4), g01 = __ldg(f + 5);
    const float g10 = __ldg(f + 6), g11 = __ldg(f + 7);

    // Input row bases: channel 2g at 2*bg planes, channel 2g+1 one plane later.
    int in_base = 2 * bg * HW_IN + h * W_IN;
    const float2* arow = reinterpret_cast<const float2*>(x + in_base);
    const float2* brow = reinterpret_cast<const float2*>(x + in_base + HW_IN);

    // Four independent 8B loads: input cols {2i,2i+1} and {64+2i,64+2i+1}
    float2 aL = __ldg(arow + i);        // channel 2g,   low half
    float2 bL = __ldg(brow + i);        // channel 2g+1, low half
    float2 aH = __ldg(arow + 32 + i);   // channel 2g,   high half
    float2 bH = __ldg(brow + 32 + i);   // channel 2g+1, high half

    // Output rows 2h, 2h+1; thread writes float4-cols i (low) and 32+i (high).
    int out_base = bg * HW_OUT + (h << 1) * W_OUT;
    float4* orow0 = reinterpret_cast<float4*>(out + out_base);
    float4* orow1 = reinterpret_cast<float4*>(out + out_base + W_OUT);

    // Low half: output cols 4i..4i+3 from input cols 2i, 2i+1
    float4 r0L = make_float4(fmaf(bL.x, g00, aL.x * f00), fmaf(bL.x, g01, aL.x * f01),
                             fmaf(bL.y, g00, aL.y * f00), fmaf(bL.y, g01, aL.y * f01));
    float4 r1L = make_float4(fmaf(bL.x, g10, aL.x * f10), fmaf(bL.x, g11, aL.x * f11),
                             fmaf(bL.y, g10, aL.y * f10), fmaf(bL.y, g11, aL.y * f11));
    // High half: output cols 128+4i..128+4i+3 from input cols 64+2i, 64+2i+1
    float4 r0H = make_float4(fmaf(bH.x, g00, aH.x * f00), fmaf(bH.x, g01, aH.x * f01),
                             fmaf(bH.y, g00, aH.y * f00), fmaf(bH.y, g01, aH.y * f01));
    float4 r1H = make_float4(fmaf(bH.x, g10, aH.x * f10), fmaf(bH.x, g11, aH.x * f11),
                             fmaf(bH.y, g10, aH.y * f10), fmaf(bH.y, g11, aH.y * f11));

    // Each store instruction: 32 lanes x 16B at stride 16B = 512B contiguous.
    orow0[i]      = r0L;
    orow0[32 + i] = r0H;
    orow1[i]      = r1L;
    orow1[32 + i] = r1H;
}

extern "C" void kernel_launch(void* const* d_in, const int* in_sizes, int n_in,
                              void* d_out, int out_size) {
    const float* x = (const float*)d_in[0];   // (16,128,128,128) f32
    const float* f = (const float*)d_in[1];   // (2,2,2) f32
    float* out = (float*)d_out;               // (16,64,256,256) f32

    const int total = 16 * 64 * 128 * 32;     // 4,194,304 threads
    const int tpb = 256;
    iwt_kernel<<<total / tpb, tpb>>>(x, f, out);
}